// round 7
// baseline (speedup 1.0000x reference)
#include <cuda_runtime.h>
#include <cstddef>

#define CB 256
#define CS 128
#define CT 128
#define CE 512
#define CH 1024
#define CHD 512
#define CV 256
#define MK (CS*CB)

#define OFF_XEMB   ((size_t)0)
#define OFF_PREA   (OFF_XEMB + (size_t)MK*CE)
#define OFF_PREB   (OFF_PREA + (size_t)MK*2048)
#define OFF_X1     (OFF_PREB + (size_t)MK*2048)
#define OFF_ENCOUT (OFF_X1 + (size_t)MK*CH)
#define OFF_ENCPROJ (OFF_ENCOUT + (size_t)MK*CH)
#define OFF_C0F    (OFF_ENCPROJ + (size_t)MK*CH)
#define OFF_C0B    (OFF_C0F + (size_t)CB*CHD)
#define OFF_C1F    (OFF_C0B + (size_t)CB*CHD)
#define OFF_C1B    (OFF_C1F + (size_t)CB*CHD)
#define OFF_DH0    (OFF_C1B + (size_t)CB*CHD)
#define OFF_DC0    (OFF_DH0 + (size_t)2*CB*CH)
#define OFF_DH1    (OFF_DC0 + (size_t)CB*CH)
#define OFF_DC1    (OFF_DH1 + (size_t)2*CB*CH)
#define OFF_Q      (OFF_DC1 + (size_t)CB*CH)
#define OFF_RIN    (OFF_Q + (size_t)CB*CH)
#define OFF_P0     (OFF_RIN + (size_t)CB*(CE+CH))
#define OFF_P1     (OFF_P0 + (size_t)CB*4096)
#define SCRATCH_FLOATS (OFF_P1 + (size_t)CB*4096)

__device__ float g_s[SCRATCH_FLOATS];
__device__ unsigned g_cnt;   // zero-initialized
__device__ unsigned g_gen;   // zero-initialized (monotonic across replays)

__device__ __forceinline__ float sg(float x){ return 1.f/(1.f+expf(-x)); }

// ---- software grid barrier (all launched blocks participate; self-resetting) ----
__device__ __forceinline__ void gbar()
{
    __syncthreads();
    if (threadIdx.x == 0) {
        __threadfence();
        unsigned gen = atomicAdd(&g_gen, 0u);
        if (atomicAdd(&g_cnt, 1u) == gridDim.x - 1u) {
            atomicExch(&g_cnt, 0u);
            __threadfence();
            atomicAdd(&g_gen, 1u);
        } else {
            while (atomicAdd(&g_gen, 0u) == gen) __nanosleep(512);
        }
        __threadfence();
    }
    __syncthreads();
}

// ---- GEMM tile: C[m][n] = A[m][:K].Bw[n][:K] + bias[n]; 64x64 tile, 256 thr ----
__device__ __forceinline__ void dev_gemm(const float* __restrict__ A, const float* __restrict__ Bw,
    const float* __restrict__ bias, float* __restrict__ C,
    int K, int lda, int ldb, long long ldc, int mBase, int nBase, float* sm)
{
    float (*sA)[68] = (float(*)[68])sm;
    float (*sB)[68] = (float(*)[68])(sm + 16*68);
    int tid = threadIdx.x, tx = tid&15, ty = tid>>4;
    int r = tid>>2, q = tid&3;
    float acc[4][4] = {};
    for (int k0 = 0; k0 < K; k0 += 16) {
        float4 av = *(const float4*)(A + (size_t)(mBase+r)*lda + k0 + 4*q);
        sA[4*q][r]=av.x; sA[4*q+1][r]=av.y; sA[4*q+2][r]=av.z; sA[4*q+3][r]=av.w;
        float4 bv = *(const float4*)(Bw + (size_t)(nBase+r)*ldb + k0 + 4*q);
        sB[4*q][r]=bv.x; sB[4*q+1][r]=bv.y; sB[4*q+2][r]=bv.z; sB[4*q+3][r]=bv.w;
        __syncthreads();
#pragma unroll
        for (int kk = 0; kk < 16; kk++) {
            float a[4], b[4];
#pragma unroll
            for (int i = 0; i < 4; i++){ a[i]=sA[kk][ty*4+i]; b[i]=sB[kk][tx*4+i]; }
#pragma unroll
            for (int i = 0; i < 4; i++)
#pragma unroll
                for (int j = 0; j < 4; j++) acc[i][j] = fmaf(a[i], b[j], acc[i][j]);
        }
        __syncthreads();
    }
#pragma unroll
    for (int i = 0; i < 4; i++) {
        long long m = mBase + ty*4 + i;
#pragma unroll
        for (int j = 0; j < 4; j++) {
            int n = nBase + tx*4 + j;
            C[m*ldc + n] = acc[i][j] + (bias ? bias[n] : 0.f);
        }
    }
}

// ---- LSTM tile: gates = pre + hprev @ whh^T, cell update; 64 j x 32 b ----
// first==true: both h_prev and c_prev are treated as zero (no stale reads).
__device__ __forceinline__ void dev_lstm(const float* __restrict__ pre, const float* __restrict__ whh,
    const float* __restrict__ hprev, float* __restrict__ c, float* __restrict__ hout,
    int HID, long long hStride, int jBase, int bBase, bool first, float* sm)
{
    float (*sW)[32][65] = (float(*)[32][65])sm;       // 4*32*65 = 8320
    float (*sH)[33]     = (float(*)[33])(sm + 8320);  // 32*33 = 1056
    int tid = threadIdx.x, tx = tid&63, ty = tid>>6;
    int j = jBase + tx;
    float acc[4][8] = {};
    for (int k0 = 0; k0 < HID; k0 += 32) {
        {
            int g = tid>>6, jj = tid&63;
            const float* wrow = whh + (size_t)(g*HID + jBase + jj)*HID + k0;
#pragma unroll
            for (int qq = 0; qq < 8; qq++) {
                float4 v = *(const float4*)(wrow + 4*qq);
                sW[g][4*qq][jj]=v.x; sW[g][4*qq+1][jj]=v.y;
                sW[g][4*qq+2][jj]=v.z; sW[g][4*qq+3][jj]=v.w;
            }
            int hb = tid>>3, hq = tid&7;
            float4 hv = make_float4(0.f,0.f,0.f,0.f);
            if (!first)
                hv = *(const float4*)(hprev + (size_t)(bBase+hb)*hStride + k0 + 4*hq);
            sH[4*hq][hb]=hv.x; sH[4*hq+1][hb]=hv.y; sH[4*hq+2][hb]=hv.z; sH[4*hq+3][hb]=hv.w;
        }
        __syncthreads();
#pragma unroll 4
        for (int kk = 0; kk < 32; kk++) {
            float h[8];
#pragma unroll
            for (int rr = 0; rr < 8; rr++) h[rr] = sH[kk][ty*8+rr];
#pragma unroll
            for (int g = 0; g < 4; g++) {
                float w = sW[g][kk][tx];
#pragma unroll
                for (int rr = 0; rr < 8; rr++) acc[g][rr] = fmaf(w, h[rr], acc[g][rr]);
            }
        }
        __syncthreads();
    }
#pragma unroll
    for (int rr = 0; rr < 8; rr++) {
        int b = bBase + ty*8 + rr;
        const float* prow = pre + (size_t)b*4*HID;
        float gi = acc[0][rr] + prow[j];
        float gf = acc[1][rr] + prow[HID + j];
        float gg = acc[2][rr] + prow[2*HID + j];
        float go = acc[3][rr] + prow[3*HID + j];
        size_t ci = (size_t)b*HID + j;
        float cprev = first ? 0.f : c[ci];
        float cn = sg(gf)*cprev + sg(gi)*tanhf(gg);
        c[ci] = cn;
        hout[(size_t)b*hStride + j] = sg(go)*tanhf(cn);
    }
}

// ---- attention for one batch row (256 threads) ----
__device__ __forceinline__ void dev_attn(int b,
    const float* __restrict__ encproj, const float* __restrict__ encout,
    const float* __restrict__ q, const float* __restrict__ w2,
    const int* __restrict__ src, const int* __restrict__ tgt,
    const float* __restrict__ dec_embed,
    float* __restrict__ rin, float* __restrict__ attn_out, int t, float* sm)
{
    float* sq = sm;            // 1024
    float* sa = sm + CH;       // 128
    int tid = threadIdx.x;
    for (int h = tid; h < CH; h += 256) sq[h] = q[(size_t)b*CH + h];
    __syncthreads();

    int warp = tid>>5, lane = tid&31;
    for (int s = warp; s < CS; s += 8) {
        const float* ep = encproj + ((size_t)b*CS + s)*CH;
        float part = 0.f;
#pragma unroll
        for (int i = 0; i < 8; i++) {
            int h = i*128 + lane*4;
            float4 e4 = *(const float4*)(ep + h);
            float4 w4 = *(const float4*)(w2 + h);
            part = fmaf(tanhf(e4.x + sq[h]),   w4.x, part);
            part = fmaf(tanhf(e4.y + sq[h+1]), w4.y, part);
            part = fmaf(tanhf(e4.z + sq[h+2]), w4.z, part);
            part = fmaf(tanhf(e4.w + sq[h+3]), w4.w, part);
        }
#pragma unroll
        for (int o = 16; o; o >>= 1) part += __shfl_xor_sync(0xffffffffu, part, o);
        if (lane == 0) sa[s] = part;
    }
    __syncthreads();

    if (warp == 0) {
        const int* sr = src + b*CS;
        float e[4];
#pragma unroll
        for (int i = 0; i < 4; i++)
            e[i] = (sr[lane + 32*i] != 0) ? sa[lane + 32*i] : -1e30f;
        float m = fmaxf(fmaxf(e[0], e[1]), fmaxf(e[2], e[3]));
#pragma unroll
        for (int o = 16; o; o >>= 1) m = fmaxf(m, __shfl_xor_sync(0xffffffffu, m, o));
        float p[4], ssum = 0.f;
#pragma unroll
        for (int i = 0; i < 4; i++){ p[i] = __expf(e[i]-m); ssum += p[i]; }
#pragma unroll
        for (int o = 16; o; o >>= 1) ssum += __shfl_xor_sync(0xffffffffu, ssum, o);
        float inv = 1.f/ssum;
        float* ao = attn_out + ((size_t)b*(CT-1) + t)*CS;
#pragma unroll
        for (int i = 0; i < 4; i++){ float v = p[i]*inv; sa[lane+32*i] = v; ao[lane+32*i] = v; }
    }
    __syncthreads();

    {
        int h = tid*4;
        float4 cx = make_float4(0.f,0.f,0.f,0.f);
        const float* eo = encout + (size_t)b*CS*CH + h;
#pragma unroll 4
        for (int s = 0; s < CS; s++) {
            float a = sa[s];
            float4 v = *(const float4*)(eo + (size_t)s*CH);
            cx.x = fmaf(a, v.x, cx.x); cx.y = fmaf(a, v.y, cx.y);
            cx.z = fmaf(a, v.z, cx.z); cx.w = fmaf(a, v.w, cx.w);
        }
        *(float4*)(rin + (size_t)b*(CE+CH) + CE + h) = cx;
    }
    if (tid < CE/4) {
        int tok = tgt[b*CT + t];
        *(float4*)(rin + (size_t)b*(CE+CH) + tid*4) =
            *(const float4*)(dec_embed + (size_t)tok*CE + tid*4);
    }
    __syncthreads();
}

// ---------------- standalone kernels ----------------
__global__ void embed_enc(const int* __restrict__ src, const float* __restrict__ emb,
                          float* __restrict__ xemb)
{
    int i4 = blockIdx.x*blockDim.x + threadIdx.x;
    if (i4 >= MK*(CE/4)) return;
    int row = i4/(CE/4), q = i4%(CE/4);
    int t = row/CB, b = row%CB;
    int tok = src[b*CS + t];
    *(float4*)(xemb + (size_t)row*CE + 4*q) =
        *(const float4*)(emb + (size_t)tok*CE + 4*q);
}

__global__ __launch_bounds__(256)
void gemm_tn(const float* A, const float* Bw, const float* bias, float* C,
             int K, int lda, int ldb, long long ldc)
{
    __shared__ float sm[2176];
    dev_gemm(A, Bw, bias, C, K, lda, ldb, ldc,
             (int)blockIdx.y*64, (int)blockIdx.x*64, sm);
}

__global__ void init_dec(const float* __restrict__ x1, const float* __restrict__ encout,
                         const float* __restrict__ c0f, const float* __restrict__ c0b,
                         const float* __restrict__ c1f, const float* __restrict__ c1b,
                         float* __restrict__ dh0, float* __restrict__ dc0,
                         float* __restrict__ dh1, float* __restrict__ dc1)
{
    int idx = blockIdx.x*blockDim.x + threadIdx.x;
    if (idx >= CB*CH) return;
    int b = idx/CH, j = idx%CH;
    float h0, h1, cc0, cc1;
    if (j < CHD) {
        h0 = x1[((size_t)(CS-1)*CB + b)*CH + j];
        h1 = encout[((size_t)b*CS + CS-1)*CH + j];
        cc0 = c0f[(size_t)b*CHD + j];
        cc1 = c1f[(size_t)b*CHD + j];
    } else {
        h0 = x1[(size_t)b*CH + j];
        h1 = encout[(size_t)b*CS*CH + j];
        cc0 = c0b[(size_t)b*CHD + j - CHD];
        cc1 = c1b[(size_t)b*CHD + j - CHD];
    }
    dh0[idx] = h0; dc0[idx] = cc0;
    dh1[idx] = h1; dc1[idx] = cc1;
}

__global__ void zero_row0(float* __restrict__ out)
{
    int idx = blockIdx.x*blockDim.x + threadIdx.x;
    if (idx >= CB*CV) return;
    out[(size_t)(idx/CV)*CT*CV + idx%CV] = 0.f;
}

// ---------------- persistent encoder scan (one bi-LSTM layer, 128 steps) ----------------
__global__ __launch_bounds__(256, 2)
void enc_scan(const float* preA, const float* preB,
              const float* whhF, const float* whhB,
              float* cF, float* cB,
              float* hbase, long long tStride, long long hStride)
{
    __shared__ float sm[9376];
    for (int s = 0; s < CS; s++) {
        for (int u = blockIdx.x; u < 128; u += gridDim.x) {
            int dir = u>>6, bt = (u>>3)&7, jt = u&7;
            int tf = s, tb = CS-1-s;
            int tt = dir ? tb : tf;
            const float* pre = dir ? preB + (size_t)tb*CB*2048 : preA + (size_t)tf*CB*2048;
            const float* whh = dir ? whhB : whhF;
            const float* hprev = nullptr;
            if (s) { int tp = dir ? tb+1 : tf-1;
                     hprev = hbase + (size_t)tp*tStride + (dir ? CHD : 0); }
            float* c    = dir ? cB : cF;
            float* hout = hbase + (size_t)tt*tStride + (dir ? CHD : 0);
            dev_lstm(pre, whh, hprev, c, hout, CHD, hStride, jt*64, bt*32,
                     s == 0, sm);
        }
        gbar();
    }
}

// ---------------- persistent decoder loop (127 steps) ----------------
__global__ __launch_bounds__(256, 2)
void dec_loop(const float* encproj, const float* encout,
              const float* attn_w1, const float* attn_b1, const float* attn_w2,
              const int* src, const int* tgt, const float* dec_embed,
              const float* dl0_wih, const float* dl0_whh, const float* dl0_b,
              const float* dl1_wih, const float* dl1_whh, const float* dl1_b,
              const float* fc_w, const float* fc_b,
              float* dh0, float* dc0, float* dh1, float* dc1,
              float* qb, float* rin, float* p0, float* p1,
              float* out, float* attn_out)
{
    __shared__ float sm[9376];
    unsigned nb = gridDim.x;
    // phase A for t=0: q = h1 @ w1_q^T + b1
    for (int u = blockIdx.x; u < 64; u += nb)
        dev_gemm(dh1, attn_w1 + CH, attn_b1, qb, CH, CH, 2*CH, CH,
                 (u/16)*64, (u%16)*64, sm);
    gbar();
    for (int t = 0; t < CT-1; t++) {
        int cur = t & 1, nxt = 1 - cur;
        float* h0c = dh0 + (size_t)cur*CB*CH; float* h0n = dh0 + (size_t)nxt*CB*CH;
        float* h1c = dh1 + (size_t)cur*CB*CH; float* h1n = dh1 + (size_t)nxt*CB*CH;
        // B: attention
        for (int u = blockIdx.x; u < CB; u += nb)
            dev_attn(u, encproj, encout, qb, attn_w2, src, tgt, dec_embed,
                     rin, attn_out, t, sm);
        gbar();
        // C: p0 = rin @ dl0_wih^T + b
        for (int u = blockIdx.x; u < 256; u += nb)
            dev_gemm(rin, dl0_wih, dl0_b, p0, CE+CH, CE+CH, CE+CH, 4096,
                     (u/64)*64, (u%64)*64, sm);
        gbar();
        // D: cell0
        for (int u = blockIdx.x; u < 128; u += nb)
            dev_lstm(p0, dl0_whh, h0c, dc0, h0n, CH, CH, (u&15)*64, (u>>4)*32,
                     false, sm);
        gbar();
        // E: p1 = h0n @ dl1_wih^T + b
        for (int u = blockIdx.x; u < 256; u += nb)
            dev_gemm(h0n, dl1_wih, dl1_b, p1, CH, CH, CH, 4096,
                     (u/64)*64, (u%64)*64, sm);
        gbar();
        // F: cell1
        for (int u = blockIdx.x; u < 128; u += nb)
            dev_lstm(p1, dl1_whh, h1c, dc1, h1n, CH, CH, (u&15)*64, (u>>4)*32,
                     false, sm);
        gbar();
        // G: logits to out[:, t+1, :]  +  A': q for next step
        for (int u = blockIdx.x; u < 80; u += nb) {
            if (u < 16)
                dev_gemm(h1n, fc_w, fc_b, out + (size_t)(t+1)*CV, CH, CH, CH,
                         (long long)CT*CV, (u/4)*64, (u%4)*64, sm);
            else if (t+1 < CT-1) {
                int v = u - 16;
                dev_gemm(h1n, attn_w1 + CH, attn_b1, qb, CH, CH, 2*CH, CH,
                         (v/16)*64, (v%16)*64, sm);
            }
        }
        gbar();
    }
}

extern "C" void kernel_launch(void* const* d_in, const int* in_sizes, int n_in,
                              void* d_out, int out_size)
{
    const int*   src       = (const int*)  d_in[0];
    const int*   tgt       = (const int*)  d_in[1];
    const float* enc_embed = (const float*)d_in[2];
    const float* dec_embed = (const float*)d_in[3];
    const float* l0f_wih=(const float*)d_in[4],  *l0f_whh=(const float*)d_in[5],  *l0f_b=(const float*)d_in[6];
    const float* l0b_wih=(const float*)d_in[7],  *l0b_whh=(const float*)d_in[8],  *l0b_b=(const float*)d_in[9];
    const float* l1f_wih=(const float*)d_in[10], *l1f_whh=(const float*)d_in[11], *l1f_b=(const float*)d_in[12];
    const float* l1b_wih=(const float*)d_in[13], *l1b_whh=(const float*)d_in[14], *l1b_b=(const float*)d_in[15];
    const float* dl0_wih=(const float*)d_in[16], *dl0_whh=(const float*)d_in[17], *dl0_b=(const float*)d_in[18];
    const float* dl1_wih=(const float*)d_in[19], *dl1_whh=(const float*)d_in[20], *dl1_b=(const float*)d_in[21];
    const float* attn_w1=(const float*)d_in[22], *attn_b1=(const float*)d_in[23];
    const float* attn_w2=(const float*)d_in[24];
    const float* fc_w=(const float*)d_in[26],    *fc_b=(const float*)d_in[27];
    float* out = (float*)d_out;

    float* S;
    cudaGetSymbolAddress((void**)&S, g_s);
    float* xemb = S+OFF_XEMB;  float* preA = S+OFF_PREA;  float* preB = S+OFF_PREB;
    float* x1 = S+OFF_X1;      float* encout = S+OFF_ENCOUT; float* encproj = S+OFF_ENCPROJ;
    float* c0f = S+OFF_C0F;    float* c0b = S+OFF_C0B;
    float* c1f = S+OFF_C1F;    float* c1b = S+OFF_C1B;
    float* dh0 = S+OFF_DH0;    float* dc0 = S+OFF_DC0;
    float* dh1 = S+OFF_DH1;    float* dc1 = S+OFF_DC1;
    float* qb = S+OFF_Q;       float* rin = S+OFF_RIN;
    float* p0 = S+OFF_P0;      float* p1 = S+OFF_P1;
    float* attn_out = out + (size_t)CB*CT*CV;

    int dev = 0; cudaGetDevice(&dev);
    int sms = 0; cudaDeviceGetAttribute(&sms, cudaDevAttrMultiProcessorCount, dev);
    int occE = 1, occD = 1;
    cudaOccupancyMaxActiveBlocksPerMultiprocessor(&occE, enc_scan, 256, 0);
    cudaOccupancyMaxActiveBlocksPerMultiprocessor(&occD, dec_loop, 256, 0);
    if (occE < 1) occE = 1;
    if (occD < 1) occD = 1;
    unsigned nbE = (unsigned)(sms * occE);
    unsigned nbD = (unsigned)(sms * occD);

    embed_enc<<<(MK*(CE/4)+255)/256, 256>>>(src, enc_embed, xemb);

    gemm_tn<<<dim3(2048/64, MK/64), 256>>>(xemb, l0f_wih, l0f_b, preA, CE, CE, CE, 2048);
    gemm_tn<<<dim3(2048/64, MK/64), 256>>>(xemb, l0b_wih, l0b_b, preB, CE, CE, CE, 2048);
    enc_scan<<<nbE, 256>>>(preA, preB, l0f_whh, l0b_whh, c0f, c0b,
                           x1, (long long)CB*CH, (long long)CH);
    gemm_tn<<<dim3(2048/64, MK/64), 256>>>(x1, l1f_wih, l1f_b, preA, CH, CH, CH, 2048);
    gemm_tn<<<dim3(2048/64, MK/64), 256>>>(x1, l1b_wih, l1b_b, preB, CH, CH, CH, 2048);
    enc_scan<<<nbE, 256>>>(preA, preB, l1f_whh, l1b_whh, c1f, c1b,
                           encout, (long long)CH, (long long)CS*CH);
    init_dec<<<(CB*CH+255)/256, 256>>>(x1, encout, c0f, c0b, c1f, c1b, dh0, dc0, dh1, dc1);
    gemm_tn<<<dim3(CH/64, MK/64), 256>>>(encout, attn_w1, nullptr, encproj, CH, CH, 2*CH, CH);
    zero_row0<<<(CB*CV+255)/256, 256>>>(out);

    dec_loop<<<nbD, 256>>>(encproj, encout, attn_w1, attn_b1, attn_w2,
                           src, tgt, dec_embed,
                           dl0_wih, dl0_whh, dl0_b, dl1_wih, dl1_whh, dl1_b,
                           fc_w, fc_b, dh0, dc0, dh1, dc1,
                           qb, rin, p0, p1, out, attn_out);
}

// round 9
// speedup vs baseline: 1.0389x; 1.0389x over previous
#include <cuda_runtime.h>
#include <cstddef>

typedef unsigned long long ull;

#define CB 256
#define CS 128
#define CT 128
#define CE 512
#define CH 1024
#define CHD 512
#define CV 256
#define MK (CS*CB)
#define KC 32

#define OFF_XEMB   ((size_t)0)
#define OFF_PREA   (OFF_XEMB + (size_t)MK*CE)
#define OFF_PREB   (OFF_PREA + (size_t)MK*2048)
#define OFF_X1     (OFF_PREB + (size_t)MK*2048)
#define OFF_ENCOUT (OFF_X1 + (size_t)MK*CH)
#define OFF_ENCPROJ (OFF_ENCOUT + (size_t)MK*CH)
#define OFF_C0F    (OFF_ENCPROJ + (size_t)MK*CH)
#define OFF_C0B    (OFF_C0F + (size_t)CB*CHD)
#define OFF_C1F    (OFF_C0B + (size_t)CB*CHD)
#define OFF_C1B    (OFF_C1F + (size_t)CB*CHD)
#define OFF_DH0    (OFF_C1B + (size_t)CB*CHD)
#define OFF_DC0    (OFF_DH0 + (size_t)2*CB*CH)
#define OFF_DH1    (OFF_DC0 + (size_t)CB*CH)
#define OFF_DC1    (OFF_DH1 + (size_t)2*CB*CH)
#define OFF_Q      (OFF_DC1 + (size_t)CB*CH)
#define OFF_RIN    (OFF_Q + (size_t)CB*CH)
#define SCRATCH_FLOATS (OFF_RIN + (size_t)CB*(CE+CH))

__device__ float g_s[SCRATCH_FLOATS];
__device__ unsigned g_cnt;   // zero-init
__device__ unsigned g_gen;   // zero-init, monotonic across replays

#define FMA2(d,a,b,c) asm("fma.rn.f32x2 %0, %1, %2, %3;" : "=l"(d) : "l"(a), "l"(b), "l"(c))

__device__ __forceinline__ void upk(ull v, float& lo, float& hi){
    asm("mov.b64 {%0,%1}, %2;" : "=f"(lo), "=f"(hi) : "l"(v));
}

// accurate fast tanh (XLA rational, ~1e-7 abs err)
__device__ __forceinline__ float tanh_acc(float x){
    float xc = fminf(fmaxf(x, -7.90531110763549805f), 7.90531110763549805f);
    float x2 = xc*xc;
    float p = fmaf(x2, -2.76076847742355e-16f, 2.00018790482477e-13f);
    p = fmaf(x2, p, -8.60467152213735e-11f);
    p = fmaf(x2, p, 5.12229709037114e-08f);
    p = fmaf(x2, p, 1.48572235717979e-05f);
    p = fmaf(x2, p, 6.37261928875436e-04f);
    p = fmaf(x2, p, 4.89352455891786e-03f);
    p = p*xc;
    float q = fmaf(x2, 1.19825839466702e-06f, 1.18534705686654e-04f);
    q = fmaf(x2, q, 2.26843463243900e-03f);
    q = fmaf(x2, q, 4.89352518554385e-03f);
    return __fdividef(p, q);
}
__device__ __forceinline__ float sgf(float x){
    return __fdividef(1.f, 1.f + __expf(-x));
}

// ---- software grid barrier ----
__device__ __forceinline__ void gbar()
{
    __syncthreads();
    if (threadIdx.x == 0) {
        __threadfence();
        unsigned gen = atomicAdd(&g_gen, 0u);
        if (atomicAdd(&g_cnt, 1u) == gridDim.x - 1u) {
            atomicExch(&g_cnt, 0u);
            __threadfence();
            atomicAdd(&g_gen, 1u);
        } else {
            while (atomicAdd(&g_gen, 0u) == gen) __nanosleep(256);
        }
        __threadfence();
    }
    __syncthreads();
}

// ============ broadcast GEMM tile: 64n x 32m, C = A.W^T + bias ============
// A[m][k] lda, W[n][k] ldb, thread: tx=n-lane(32) x 2 strips, ty=m-oct(8) -> 4 m as 2 f32x2
__device__ __forceinline__ void gemm_core(
    const float* __restrict__ A, int lda,
    const float* __restrict__ W, int ldb, int K,
    const float* __restrict__ bias, float* __restrict__ C, long long ldc,
    int mBase, int nBase, float2* smw, float* smh)
{
    int tid = threadIdx.x, tx = tid & 31, ty = tid >> 5;
    ull acc[2][2] = {};
    for (int k0 = 0; k0 < K; k0 += KC) {
        {
            int fid = tid;            // 512 float4 total, 2 per thread
#pragma unroll
            for (int i = 0; i < 2; i++) {
                int s = fid >> 8, r = (fid >> 3) & 31, q = fid & 7;
                float4 v = *(const float4*)(W + (size_t)(nBase + s*32 + r)*ldb + k0 + 4*q);
                float2* d0 = smw + (s*KC + 4*q)*33 + r;
                d0[0]  = make_float2(v.x, v.x);
                d0[33] = make_float2(v.y, v.y);
                d0[66] = make_float2(v.z, v.z);
                d0[99] = make_float2(v.w, v.w);
                fid += 256;
            }
            int r = tid >> 3, q = tid & 7;
            float4 v = *(const float4*)(A + (size_t)(mBase + r)*lda + k0 + 4*q);
            smh[(4*q+0)*34 + r] = v.x;
            smh[(4*q+1)*34 + r] = v.y;
            smh[(4*q+2)*34 + r] = v.z;
            smh[(4*q+3)*34 + r] = v.w;
        }
        __syncthreads();
#pragma unroll 8
        for (int kk = 0; kk < KC; kk++) {
            ull h0 = *(const ull*)(smh + kk*34 + ty*4);
            ull h1 = *(const ull*)(smh + kk*34 + ty*4 + 2);
#pragma unroll
            for (int s = 0; s < 2; s++) {
                ull w = *(const ull*)&smw[(s*KC + kk)*33 + tx];
                FMA2(acc[s][0], w, h0, acc[s][0]);
                FMA2(acc[s][1], w, h1, acc[s][1]);
            }
        }
        __syncthreads();
    }
#pragma unroll
    for (int s = 0; s < 2; s++) {
        int n = nBase + s*32 + tx;
        float bz = bias ? bias[n] : 0.f;
#pragma unroll
        for (int p = 0; p < 2; p++) {
            float lo, hi; upk(acc[s][p], lo, hi);
            long long m = mBase + ty*4 + 2*p;
            C[m*ldc + n]     = lo + bz;
            C[(m+1)*ldc + n] = hi + bz;
        }
    }
}

// ============ fused LSTM cell tile: 32j x 32b, all 4 gates ============
// gates = A1@W1^T + A2@W2^T (+pre)(+bias); epilogue writes c, hout.
__device__ __forceinline__ void cell_core(
    const float* __restrict__ A1, int lda1, int K1, const float* __restrict__ W1,
    const float* __restrict__ A2, int lda2, int K2, const float* __restrict__ W2,
    const float* __restrict__ pre, const float* __restrict__ bias, int HID,
    float* __restrict__ c, float* __restrict__ hout, long long hStride,
    int jBase, int bBase, bool firstC, float2* smw, float* smh)
{
    int tid = threadIdx.x, tx = tid & 31, ty = tid >> 5;
    ull acc[4][2] = {};
#pragma unroll 1
    for (int seg = 0; seg < 2; seg++) {
        const float* A = seg ? A2 : A1;
        const float* W = seg ? W2 : W1;
        int K   = seg ? K2 : K1;
        int lda = seg ? lda2 : lda1;
        if (!A) continue;
        for (int k0 = 0; k0 < K; k0 += KC) {
            {
                int fid = tid;        // 1024 float4 total, 4 per thread
#pragma unroll
                for (int i = 0; i < 4; i++) {
                    int g = fid >> 8, r = (fid >> 3) & 31, q = fid & 7;
                    float4 v = *(const float4*)(W + (size_t)(g*HID + jBase + r)*K + k0 + 4*q);
                    float2* d0 = smw + (g*KC + 4*q)*33 + r;
                    d0[0]  = make_float2(v.x, v.x);
                    d0[33] = make_float2(v.y, v.y);
                    d0[66] = make_float2(v.z, v.z);
                    d0[99] = make_float2(v.w, v.w);
                    fid += 256;
                }
                int r = tid >> 3, q = tid & 7;
                float4 v = *(const float4*)(A + (size_t)(bBase + r)*lda + k0 + 4*q);
                smh[(4*q+0)*34 + r] = v.x;
                smh[(4*q+1)*34 + r] = v.y;
                smh[(4*q+2)*34 + r] = v.z;
                smh[(4*q+3)*34 + r] = v.w;
            }
            __syncthreads();
#pragma unroll 8
            for (int kk = 0; kk < KC; kk++) {
                ull h0 = *(const ull*)(smh + kk*34 + ty*4);
                ull h1 = *(const ull*)(smh + kk*34 + ty*4 + 2);
#pragma unroll
                for (int g = 0; g < 4; g++) {
                    ull w = *(const ull*)&smw[(g*KC + kk)*33 + tx];
                    FMA2(acc[g][0], w, h0, acc[g][0]);
                    FMA2(acc[g][1], w, h1, acc[g][1]);
                }
            }
            __syncthreads();
        }
    }
    int j = jBase + tx;
#pragma unroll
    for (int p = 0; p < 2; p++) {
        float i0,i1,f0,f1,g0,g1,o0,o1;
        upk(acc[0][p], i0, i1);
        upk(acc[1][p], f0, f1);
        upk(acc[2][p], g0, g1);
        upk(acc[3][p], o0, o1);
#pragma unroll
        for (int h2 = 0; h2 < 2; h2++) {
            int b = bBase + ty*4 + 2*p + h2;
            float gi = h2 ? i1 : i0;
            float gf = h2 ? f1 : f0;
            float gg = h2 ? g1 : g0;
            float go = h2 ? o1 : o0;
            if (pre) {
                const float* pr = pre + (size_t)b*4*HID;
                gi += pr[j]; gf += pr[HID + j];
                gg += pr[2*HID + j]; go += pr[3*HID + j];
            }
            if (bias) {
                gi += bias[j]; gf += bias[HID + j];
                gg += bias[2*HID + j]; go += bias[3*HID + j];
            }
            float cprev = firstC ? 0.f : c[(size_t)b*HID + j];
            float cn = sgf(gf)*cprev + sgf(gi)*tanh_acc(gg);
            c[(size_t)b*HID + j] = cn;
            hout[(size_t)b*hStride + j] = sgf(go)*tanh_acc(cn);
        }
    }
}

// ---- attention for one batch row (256 threads) ----
__device__ __forceinline__ void dev_attn(int b,
    const float* __restrict__ encproj, const float* __restrict__ encout,
    const float* __restrict__ q, const float* __restrict__ w2,
    const int* __restrict__ src, const int* __restrict__ tgt,
    const float* __restrict__ dec_embed,
    float* __restrict__ rin, float* __restrict__ attn_out, int t, float* sm)
{
    float* sq = sm;
    float* sa = sm + CH;
    int tid = threadIdx.x;
    for (int h = tid; h < CH; h += 256) sq[h] = q[(size_t)b*CH + h];
    __syncthreads();

    int warp = tid>>5, lane = tid&31;
    for (int s = warp; s < CS; s += 8) {
        const float* ep = encproj + ((size_t)b*CS + s)*CH;
        float part = 0.f;
#pragma unroll
        for (int i = 0; i < 8; i++) {
            int h = i*128 + lane*4;
            float4 e4 = *(const float4*)(ep + h);
            float4 w4 = *(const float4*)(w2 + h);
            part = fmaf(tanh_acc(e4.x + sq[h]),   w4.x, part);
            part = fmaf(tanh_acc(e4.y + sq[h+1]), w4.y, part);
            part = fmaf(tanh_acc(e4.z + sq[h+2]), w4.z, part);
            part = fmaf(tanh_acc(e4.w + sq[h+3]), w4.w, part);
        }
#pragma unroll
        for (int o = 16; o; o >>= 1) part += __shfl_xor_sync(0xffffffffu, part, o);
        if (lane == 0) sa[s] = part;
    }
    __syncthreads();

    if (warp == 0) {
        const int* sr = src + b*CS;
        float e[4];
#pragma unroll
        for (int i = 0; i < 4; i++)
            e[i] = (sr[lane + 32*i] != 0) ? sa[lane + 32*i] : -1e30f;
        float m = fmaxf(fmaxf(e[0], e[1]), fmaxf(e[2], e[3]));
#pragma unroll
        for (int o = 16; o; o >>= 1) m = fmaxf(m, __shfl_xor_sync(0xffffffffu, m, o));
        float p[4], ssum = 0.f;
#pragma unroll
        for (int i = 0; i < 4; i++){ p[i] = __expf(e[i]-m); ssum += p[i]; }
#pragma unroll
        for (int o = 16; o; o >>= 1) ssum += __shfl_xor_sync(0xffffffffu, ssum, o);
        float inv = __fdividef(1.f, ssum);
        float* ao = attn_out + ((size_t)b*(CT-1) + t)*CS;
#pragma unroll
        for (int i = 0; i < 4; i++){ float v = p[i]*inv; sa[lane+32*i] = v; ao[lane+32*i] = v; }
    }
    __syncthreads();

    {
        int h = tid*4;
        float4 cx = make_float4(0.f,0.f,0.f,0.f);
        const float* eo = encout + (size_t)b*CS*CH + h;
#pragma unroll 4
        for (int s = 0; s < CS; s++) {
            float a = sa[s];
            float4 v = *(const float4*)(eo + (size_t)s*CH);
            cx.x = fmaf(a, v.x, cx.x); cx.y = fmaf(a, v.y, cx.y);
            cx.z = fmaf(a, v.z, cx.z); cx.w = fmaf(a, v.w, cx.w);
        }
        *(float4*)(rin + (size_t)b*(CE+CH) + CE + h) = cx;
    }
    if (tid < CE/4) {
        int tok = tgt[b*CT + t];
        *(float4*)(rin + (size_t)b*(CE+CH) + tid*4) =
            *(const float4*)(dec_embed + (size_t)tok*CE + tid*4);
    }
    __syncthreads();
}

// ---------------- standalone kernels ----------------
__global__ void embed_enc(const int* __restrict__ src, const float* __restrict__ emb,
                          float* __restrict__ xemb)
{
    int i4 = blockIdx.x*blockDim.x + threadIdx.x;
    if (i4 >= MK*(CE/4)) return;
    int row = i4/(CE/4), q = i4%(CE/4);
    int t = row/CB, b = row%CB;
    int tok = src[b*CS + t];
    *(float4*)(xemb + (size_t)row*CE + 4*q) =
        *(const float4*)(emb + (size_t)tok*CE + 4*q);
}

__global__ __launch_bounds__(256)
void gemm_b_k(const float* A, int lda, const float* W, int ldb, int K,
              const float* bias, float* C, long long ldc)
{
    __shared__ __align__(16) float sm[2*KC*33*2 + KC*34];
    gemm_core(A, lda, W, ldb, K, bias, C, ldc,
              (int)blockIdx.y*32, (int)blockIdx.x*64, (float2*)sm, sm + 2*KC*33*2);
}

__global__ void init_dec(const float* __restrict__ x1, const float* __restrict__ encout,
                         const float* __restrict__ c0f, const float* __restrict__ c0b,
                         const float* __restrict__ c1f, const float* __restrict__ c1b,
                         float* __restrict__ dh0, float* __restrict__ dc0,
                         float* __restrict__ dh1, float* __restrict__ dc1)
{
    int idx = blockIdx.x*blockDim.x + threadIdx.x;
    if (idx >= CB*CH) return;
    int b = idx/CH, j = idx%CH;
    float h0, h1, cc0, cc1;
    if (j < CHD) {
        h0 = x1[((size_t)(CS-1)*CB + b)*CH + j];
        h1 = encout[((size_t)b*CS + CS-1)*CH + j];
        cc0 = c0f[(size_t)b*CHD + j];
        cc1 = c1f[(size_t)b*CHD + j];
    } else {
        h0 = x1[(size_t)b*CH + j];
        h1 = encout[(size_t)b*CS*CH + j];
        cc0 = c0b[(size_t)b*CHD + j - CHD];
        cc1 = c1b[(size_t)b*CHD + j - CHD];
    }
    dh0[idx] = h0; dc0[idx] = cc0;
    dh1[idx] = h1; dc1[idx] = cc1;
}

__global__ void zero_row0(float* __restrict__ out)
{
    int idx = blockIdx.x*blockDim.x + threadIdx.x;
    if (idx >= CB*CV) return;
    out[(size_t)(idx/CV)*CT*CV + idx%CV] = 0.f;
}

// ---------------- persistent encoder scan ----------------
__global__ __launch_bounds__(256, 2)
void enc_scan(const float* preA, const float* preB,
              const float* whhF, const float* whhB,
              float* cF, float* cB,
              float* hbase, long long tStride, long long hStride)
{
    __shared__ __align__(16) float sm[4*KC*33*2 + KC*34];
    float2* smw = (float2*)sm;
    float*  smh = sm + 4*KC*33*2;
    for (int s = 0; s < CS; s++) {
        int tf = s, tb = CS-1-s;
        for (int u = blockIdx.x; u < 256; u += gridDim.x) {
            int dir = u >> 7, jt = (u >> 3) & 15, bt = u & 7;
            int tt = dir ? tb : tf;
            const float* pre = dir ? preB + (size_t)tb*CB*2048 : preA + (size_t)tf*CB*2048;
            const float* whh = dir ? whhB : whhF;
            const float* hprev = nullptr;
            if (s) { int tp = dir ? tb+1 : tf-1;
                     hprev = hbase + (size_t)tp*tStride + (dir ? CHD : 0); }
            float* c    = dir ? cB : cF;
            float* hout = hbase + (size_t)tt*tStride + (dir ? CHD : 0);
            cell_core(hprev, (int)hStride, CHD, whh,
                      nullptr, 0, 0, nullptr,
                      pre, nullptr, CHD,
                      c, hout, hStride, jt*32, bt*32, s == 0, smw, smh);
        }
        gbar();
    }
}

// ---------------- persistent decoder loop ----------------
__global__ __launch_bounds__(256, 2)
void dec_loop(const float* encproj, const float* encout,
              const float* attn_w1, const float* attn_b1, const float* attn_w2,
              const int* src, const int* tgt, const float* dec_embed,
              const float* dl0_wih, const float* dl0_whh, const float* dl0_b,
              const float* dl1_wih, const float* dl1_whh, const float* dl1_b,
              const float* fc_w, const float* fc_b,
              float* dh0, float* dc0, float* dh1, float* dc1,
              float* qb, float* rin, float* out, float* attn_out)
{
    __shared__ __align__(16) float sm[4*KC*33*2 + KC*34];
    float2* smw = (float2*)sm;
    float*  smh = sm + 4*KC*33*2;
    unsigned nb = gridDim.x;

    // initial q = h1 @ w1_q^T + b1 (128 tiles)
    for (int u = blockIdx.x; u < 128; u += nb)
        gemm_core(dh1, CH, attn_w1 + CH, 2*CH, CH, attn_b1, qb, CH,
                  (u >> 4)*32, (u & 15)*64, smw, smh);
    gbar();

    for (int t = 0; t < CT-1; t++) {
        int cur = t & 1, nxt = 1 - cur;
        float* h0c = dh0 + (size_t)cur*CB*CH; float* h0n = dh0 + (size_t)nxt*CB*CH;
        float* h1c = dh1 + (size_t)cur*CB*CH; float* h1n = dh1 + (size_t)nxt*CB*CH;

        // B: attention (256 rows)
        for (int u = blockIdx.x; u < CB; u += nb)
            dev_attn(u, encproj, encout, qb, attn_w2, src, tgt, dec_embed,
                     rin, attn_out, t, sm);
        gbar();

        // C: fused cell0: gates = rin@wih0 + h0c@whh0 + b0 (256 tiles)
        for (int u = blockIdx.x; u < 256; u += nb)
            cell_core(rin, CE+CH, CE+CH, dl0_wih,
                      h0c, CH, CH, dl0_whh,
                      nullptr, dl0_b, CH,
                      dc0, h0n, CH, (u >> 3)*32, (u & 7)*32, false, smw, smh);
        gbar();

        // E: fused cell1: gates = h0n@wih1 + h1c@whh1 + b1 (256 tiles)
        for (int u = blockIdx.x; u < 256; u += nb)
            cell_core(h0n, CH, CH, dl1_wih,
                      h1c, CH, CH, dl1_whh,
                      nullptr, dl1_b, CH,
                      dc1, h1n, CH, (u >> 3)*32, (u & 7)*32, false, smw, smh);
        gbar();

        // G: logits (32 tiles) + next q (128 tiles)
        for (int u = blockIdx.x; u < 160; u += nb) {
            if (u < 32)
                gemm_core(h1n, CH, fc_w, CH, CH, fc_b,
                          out + (size_t)(t+1)*CV, (long long)CT*CV,
                          (u >> 2)*32, (u & 3)*64, smw, smh);
            else {
                int v = u - 32;
                gemm_core(h1n, CH, attn_w1 + CH, 2*CH, CH, attn_b1, qb, CH,
                          (v >> 4)*32, (v & 15)*64, smw, smh);
            }
        }
        gbar();
    }
}

extern "C" void kernel_launch(void* const* d_in, const int* in_sizes, int n_in,
                              void* d_out, int out_size)
{
    const int*   src       = (const int*)  d_in[0];
    const int*   tgt       = (const int*)  d_in[1];
    const float* enc_embed = (const float*)d_in[2];
    const float* dec_embed = (const float*)d_in[3];
    const float* l0f_wih=(const float*)d_in[4],  *l0f_whh=(const float*)d_in[5],  *l0f_b=(const float*)d_in[6];
    const float* l0b_wih=(const float*)d_in[7],  *l0b_whh=(const float*)d_in[8],  *l0b_b=(const float*)d_in[9];
    const float* l1f_wih=(const float*)d_in[10], *l1f_whh=(const float*)d_in[11], *l1f_b=(const float*)d_in[12];
    const float* l1b_wih=(const float*)d_in[13], *l1b_whh=(const float*)d_in[14], *l1b_b=(const float*)d_in[15];
    const float* dl0_wih=(const float*)d_in[16], *dl0_whh=(const float*)d_in[17], *dl0_b=(const float*)d_in[18];
    const float* dl1_wih=(const float*)d_in[19], *dl1_whh=(const float*)d_in[20], *dl1_b=(const float*)d_in[21];
    const float* attn_w1=(const float*)d_in[22], *attn_b1=(const float*)d_in[23];
    const float* attn_w2=(const float*)d_in[24];
    const float* fc_w=(const float*)d_in[26],    *fc_b=(const float*)d_in[27];
    float* out = (float*)d_out;

    float* S;
    cudaGetSymbolAddress((void**)&S, g_s);
    float* xemb = S+OFF_XEMB;  float* preA = S+OFF_PREA;  float* preB = S+OFF_PREB;
    float* x1 = S+OFF_X1;      float* encout = S+OFF_ENCOUT; float* encproj = S+OFF_ENCPROJ;
    float* c0f = S+OFF_C0F;    float* c0b = S+OFF_C0B;
    float* c1f = S+OFF_C1F;    float* c1b = S+OFF_C1B;
    float* dh0 = S+OFF_DH0;    float* dc0 = S+OFF_DC0;
    float* dh1 = S+OFF_DH1;    float* dc1 = S+OFF_DC1;
    float* qb = S+OFF_Q;       float* rin = S+OFF_RIN;
    float* attn_out = out + (size_t)CB*CT*CV;

    int dev = 0; cudaGetDevice(&dev);
    int sms = 0; cudaDeviceGetAttribute(&sms, cudaDevAttrMultiProcessorCount, dev);
    int occE = 1, occD = 1;
    cudaOccupancyMaxActiveBlocksPerMultiprocessor(&occE, enc_scan, 256, 0);
    cudaOccupancyMaxActiveBlocksPerMultiprocessor(&occD, dec_loop, 256, 0);
    if (occE < 1) occE = 1;
    if (occD < 1) occD = 1;
    unsigned nbE = (unsigned)(sms * occE);
    unsigned nbD = (unsigned)(sms * occD);

    embed_enc<<<(MK*(CE/4)+255)/256, 256>>>(src, enc_embed, xemb);

    // encoder layer0 pre-projections
    gemm_b_k<<<dim3(2048/64, MK/32), 256>>>(xemb, CE, l0f_wih, CE, CE, l0f_b, preA, 2048);
    gemm_b_k<<<dim3(2048/64, MK/32), 256>>>(xemb, CE, l0b_wih, CE, CE, l0b_b, preB, 2048);
    enc_scan<<<nbE, 256>>>(preA, preB, l0f_whh, l0b_whh, c0f, c0b,
                           x1, (long long)CB*CH, (long long)CH);
    // encoder layer1 pre-projections
    gemm_b_k<<<dim3(2048/64, MK/32), 256>>>(x1, CH, l1f_wih, CH, CH, l1f_b, preA, 2048);
    gemm_b_k<<<dim3(2048/64, MK/32), 256>>>(x1, CH, l1b_wih, CH, CH, l1b_b, preB, 2048);
    enc_scan<<<nbE, 256>>>(preA, preB, l1f_whh, l1b_whh, c1f, c1b,
                           encout, (long long)CH, (long long)CS*CH);

    init_dec<<<(CB*CH+255)/256, 256>>>(x1, encout, c0f, c0b, c1f, c1b, dh0, dc0, dh1, dc1);
    // enc_proj = encout @ w1_enc^T
    gemm_b_k<<<dim3(CH/64, MK/32), 256>>>(encout, CH, attn_w1, 2*CH, CH, nullptr, encproj, CH);
    zero_row0<<<(CB*CV+255)/256, 256>>>(out);

    dec_loop<<<nbD, 256>>>(encproj, encout, attn_w1, attn_b1, attn_w2,
                           src, tgt, dec_embed,
                           dl0_wih, dl0_whh, dl0_b, dl1_wih, dl1_whh, dl1_b,
                           fc_w, fc_b, dh0, dc0, dh1, dc1,
                           qb, rin, out, attn_out);
}